// round 1
// baseline (speedup 1.0000x reference)
#include <cuda_runtime.h>
#include <math.h>

#define NN 2048
#define DD 64
#define PP 32
#define NSTOP 512
#define KIN 4131          // 2*N + 3 + P
#define KPAD 4160         // padded K (multiple of 8, zeros beyond KIN)

// ---------------- scratch (device globals: allocation-free) ----------------
__device__ __align__(16) float d_xn[NN * DD];
__device__ int   d_keep[NN];
__device__ __align__(16) float d_aggn[NN * DD];   // (adj@emb)/deg
__device__ float d_pref[NN * PP];
__device__ float d_av[NN];
__device__ float d_bv[NN];
__device__ __align__(16) float d_comb[(size_t)NN * KPAD];
__device__ __align__(16) float d_wpad[(size_t)NN * KPAD];

// ---------------- keep mask ----------------
__global__ void k_zero_keep() {
    int i = blockIdx.x * blockDim.x + threadIdx.x;
    if (i < NN) d_keep[i] = 0;
}
__global__ void k_scatter(const int* __restrict__ stops) {
    int i = blockIdx.x * blockDim.x + threadIdx.x;
    if (i < NSTOP) d_keep[stops[i]] = 1;
}

// ---------------- row-normalize embeddings ----------------
__global__ void k_norm(const float* __restrict__ emb) {
    int i = blockIdx.x;
    int t = threadIdx.x;                 // 64 threads
    float v = emb[i * DD + t];
    float s = v * v;
    #pragma unroll
    for (int o = 16; o; o >>= 1) s += __shfl_down_sync(0xffffffffu, s, o);
    __shared__ float ws[2];
    if ((t & 31) == 0) ws[t >> 5] = s;
    __syncthreads();
    float norm = fmaxf(sqrtf(ws[0] + ws[1]), 1e-8f);
    d_xn[i * DD + t] = v / norm;
}

// ---------------- adjacency row + mean aggregation, fused ----------------
// block i: build bitmap of kept neighbors j with sim(i,j)>0.5, count deg,
// then agg[i] = sum_j emb[j] / max(deg,1).
__global__ void k_agg(const float* __restrict__ emb) {
    int i = blockIdx.x;
    int t = threadIdx.x;                 // 256 threads
    if (!d_keep[i]) {                    // row of adj is all zero -> agg = 0
        if (t < DD) d_aggn[i * DD + t] = 0.f;
        return;
    }
    __shared__ __align__(16) float xi[DD];
    __shared__ unsigned mw[NN / 32];
    __shared__ int degs;
    __shared__ float aggp[256];

    if (t < DD) xi[t] = d_xn[i * DD + t];
    for (int w = t; w < NN / 32; w += 256) mw[w] = 0u;
    if (t == 0) degs = 0;
    __syncthreads();

    int cnt = 0;
    const float4* xi4 = (const float4*)xi;
    for (int j = t; j < NN; j += 256) {
        if (j == i || !d_keep[j]) continue;
        const float4* xj = (const float4*)(d_xn + j * DD);
        float s = 0.f;
        #pragma unroll
        for (int q = 0; q < DD / 4; q++) {
            float4 a = xj[q], b = xi4[q];
            s += a.x * b.x + a.y * b.y + a.z * b.z + a.w * b.w;
        }
        if (s > 0.5f) { atomicOr(&mw[j >> 5], 1u << (j & 31)); cnt++; }
    }
    if (cnt) atomicAdd(&degs, cnt);
    __syncthreads();

    float deg = fmaxf((float)degs, 1.0f);
    int d = t & (DD - 1);
    int g = t >> 6;                      // 4 j-groups of 64 dims
    float p = 0.f;
    for (int j = g; j < NN; j += 4) {
        if ((mw[j >> 5] >> (j & 31)) & 1u) p += emb[j * DD + d];
    }
    aggp[t] = p;
    __syncthreads();
    if (t < DD) {
        float s = aggp[t] + aggp[t + 64] + aggp[t + 128] + aggp[t + 192];
        d_aggn[i * DD + t] = s / deg;
    }
}

// ---------------- pref = agg@lin_l^T + b + emb@lin_r^T ; a,b edge vectors ----
__global__ void k_pref(const float* __restrict__ emb,
                       const float* __restrict__ llw, const float* __restrict__ llb,
                       const float* __restrict__ lrw, const float* __restrict__ ew) {
    int i = blockIdx.x;
    int p = threadIdx.x;                 // 32 threads (one warp)
    float s = llb[p];
    const float* ai = d_aggn + i * DD;
    const float* ei = emb + i * DD;
    #pragma unroll
    for (int d = 0; d < DD; d++)
        s += ai[d] * llw[p * DD + d] + ei[d] * lrw[p * DD + d];
    d_pref[i * PP + p] = s;
    float a = s * ew[p];
    float b = s * ew[PP + p];
    #pragma unroll
    for (int o = 16; o; o >>= 1) {
        a += __shfl_down_sync(0xffffffffu, a, o);
        b += __shfl_down_sync(0xffffffffu, b, o);
    }
    if (p == 0) { d_av[i] = a; d_bv[i] = b; }
}

// ---------------- materialize padded "combined" matrix [N, KPAD] ----------------
__global__ void k_fill_comb(const float* __restrict__ dist,
                            const float* __restrict__ edge_b,
                            const int* __restrict__ wk, const int* __restrict__ vh) {
    int idx = blockIdx.x * blockDim.x + threadIdx.x;
    if (idx >= NN * KPAD) return;
    int i = idx / KPAD;
    int k = idx - i * KPAD;
    float v;
    if (k < PP) {
        v = d_pref[i * PP + k];
    } else if (k < PP + NN) {
        float e = d_av[i] + d_bv[k - PP] + edge_b[0];
        v = (e >= 0.f) ? e : 0.01f * e;            // LeakyReLU
    } else if (k < PP + 2 * NN) {
        v = dist[(size_t)i * NN + (k - PP - NN)];
    } else if (k == PP + 2 * NN) {
        v = (float)wk[0];
    } else if (k == PP + 2 * NN + 1) {
        v = (float)vh[0];
    } else if (k == PP + 2 * NN + 2) {
        v = d_keep[i] ? 1.f : 0.f;
    } else {
        v = 0.f;                                   // zero padding
    }
    d_comb[idx] = v;
}

// ---------------- materialize padded comb_w [N, KPAD] ----------------
__global__ void k_fill_w(const float* __restrict__ combw) {
    int idx = blockIdx.x * blockDim.x + threadIdx.x;
    if (idx >= NN * KPAD) return;
    int i = idx / KPAD;
    int k = idx - i * KPAD;
    d_wpad[idx] = (k < KIN) ? combw[(size_t)i * KIN + k] : 0.f;
}

// ---------------- SGEMM: out[i][r] = sum_k comb[i][k] * wpad[r][k] + bias[r] ---
// 128x128 tile, BK=8, 256 threads, 8x8 per-thread microtile.
__global__ __launch_bounds__(256) void k_gemm(const float* __restrict__ bias,
                                              float* __restrict__ C) {
    const int BK = 8;
    __shared__ __align__(16) float As[BK][128];
    __shared__ __align__(16) float Bs[BK][128];

    int t = threadIdx.x;
    int brow = blockIdx.y * 128;
    int bcol = blockIdx.x * 128;

    int lr = t >> 1;             // 0..127 : tile row to load
    int lk = (t & 1) * 4;        // 0 or 4 : k-quad
    int tx = t & 15;             // 0..15
    int ty = t >> 4;             // 0..15

    const float* Abase = d_comb + (size_t)(brow + lr) * KPAD + lk;
    const float* Bbase = d_wpad + (size_t)(bcol + lr) * KPAD + lk;

    float acc[8][8];
    #pragma unroll
    for (int m = 0; m < 8; m++)
        #pragma unroll
        for (int n = 0; n < 8; n++) acc[m][n] = 0.f;

    for (int k0 = 0; k0 < KPAD; k0 += BK) {
        float4 a4 = *(const float4*)(Abase + k0);
        float4 b4 = *(const float4*)(Bbase + k0);
        As[lk + 0][lr] = a4.x; As[lk + 1][lr] = a4.y;
        As[lk + 2][lr] = a4.z; As[lk + 3][lr] = a4.w;
        Bs[lk + 0][lr] = b4.x; Bs[lk + 1][lr] = b4.y;
        Bs[lk + 2][lr] = b4.z; Bs[lk + 3][lr] = b4.w;
        __syncthreads();
        #pragma unroll
        for (int k = 0; k < BK; k++) {
            float ra[8], rb[8];
            #pragma unroll
            for (int m = 0; m < 8; m++) ra[m] = As[k][ty * 8 + m];
            #pragma unroll
            for (int n = 0; n < 8; n++) rb[n] = Bs[k][tx * 8 + n];
            #pragma unroll
            for (int m = 0; m < 8; m++)
                #pragma unroll
                for (int n = 0; n < 8; n++) acc[m][n] += ra[m] * rb[n];
        }
        __syncthreads();
    }

    #pragma unroll
    for (int m = 0; m < 8; m++) {
        int row = brow + ty * 8 + m;
        #pragma unroll
        for (int n = 0; n < 8; n++) {
            int col = bcol + tx * 8 + n;
            C[(size_t)row * NN + col] = acc[m][n] + bias[col];
        }
    }
}

// ---------------- in-place row log-softmax ----------------
__global__ void k_lsm(float* __restrict__ out) {
    int i = blockIdx.x;
    int t = threadIdx.x;                 // 256
    __shared__ float row[NN];
    __shared__ float red[256];

    float m = -1e30f;
    for (int j = t; j < NN; j += 256) {
        float v = out[(size_t)i * NN + j];
        row[j] = v;
        m = fmaxf(m, v);
    }
    red[t] = m;
    __syncthreads();
    #pragma unroll
    for (int o = 128; o; o >>= 1) {
        if (t < o) red[t] = fmaxf(red[t], red[t + o]);
        __syncthreads();
    }
    float mx = red[0];
    __syncthreads();

    float s = 0.f;
    for (int j = t; j < NN; j += 256) s += expf(row[j] - mx);
    red[t] = s;
    __syncthreads();
    #pragma unroll
    for (int o = 128; o; o >>= 1) {
        if (t < o) red[t] += red[t + o];
        __syncthreads();
    }
    float lse = logf(red[0]) + mx;

    for (int j = t; j < NN; j += 256) out[(size_t)i * NN + j] = row[j] - lse;
}

// ---------------- launch ----------------
extern "C" void kernel_launch(void* const* d_in, const int* in_sizes, int n_in,
                              void* d_out, int out_size) {
    const float* dist   = (const float*)d_in[0];
    const float* emb    = (const float*)d_in[1];
    const float* llw    = (const float*)d_in[2];
    const float* llb    = (const float*)d_in[3];
    const float* lrw    = (const float*)d_in[4];
    const float* ew     = (const float*)d_in[5];
    const float* edge_b = (const float*)d_in[6];
    const float* combw  = (const float*)d_in[7];
    const float* combb  = (const float*)d_in[8];
    const int*   stops  = (const int*)d_in[9];
    const int*   wk     = (const int*)d_in[10];
    const int*   vh     = (const int*)d_in[11];
    float* out = (float*)d_out;

    k_zero_keep<<<(NN + 255) / 256, 256>>>();
    k_scatter<<<(NSTOP + 255) / 256, 256>>>(stops);
    k_norm<<<NN, DD>>>(emb);
    k_agg<<<NN, 256>>>(emb);
    k_pref<<<NN, PP>>>(emb, llw, llb, lrw, ew);

    int tot = NN * KPAD;
    k_fill_comb<<<(tot + 255) / 256, 256>>>(dist, edge_b, wk, vh);
    k_fill_w<<<(tot + 255) / 256, 256>>>(combw);

    dim3 gg(NN / 128, NN / 128);
    k_gemm<<<gg, 256>>>(combb, out);

    k_lsm<<<NN, 256>>>(out);
}

// round 3
// speedup vs baseline: 3.1613x; 3.1613x over previous
#include <cuda_runtime.h>
#include <math.h>
#include <stdint.h>

#define NN 2048
#define DD 64
#define PP 32
#define NSTOP 512
#define KIN 4131          // 2*N + 3 + P
#define KPAD 4160         // 130 chunks of 32
#define NCHUNK 130
#define BM 128
#define BN 128
#define BK 32
#define NSTG 3
#define TILE_FLOATS 4096          // BM*BK == BN*BK
#define STAGE_FLOATS 8192
#define GEMM_SMEM (NSTG * STAGE_FLOATS * 4)

// ---------------- scratch (device globals: allocation-free) ----------------
__device__ __align__(16) float d_xn[NN * DD];
__device__ int   d_keep[NN];
__device__ __align__(16) float d_aggn[NN * DD];
__device__ float d_pref[NN * PP];
__device__ float d_av[NN];
__device__ float d_bv[NN];
// operands pre-packed in mma-fragment order, tf32-converted
__device__ __align__(128) uint32_t d_apack[(size_t)NN * KPAD];
__device__ __align__(128) uint32_t d_bpack[(size_t)NN * KPAD];

// ---------------- helpers ----------------
__device__ __forceinline__ uint32_t smem_u32(const void* p) {
    uint32_t a;
    asm("{ .reg .u64 t; cvta.to.shared.u64 t, %1; cvt.u32.u64 %0, t; }" : "=r"(a) : "l"(p));
    return a;
}
__device__ __forceinline__ uint32_t f2tf32(float f) {
    uint32_t r;
    asm("cvt.rna.tf32.f32 %0, %1;" : "=r"(r) : "f"(f));
    return r;
}
#define CP_ASYNC16(dst, src) \
    asm volatile("cp.async.cg.shared.global [%0], [%1], 16;" :: "r"(dst), "l"(src) : "memory")
#define CP_COMMIT() asm volatile("cp.async.commit_group;" ::: "memory")
#define CP_WAIT(n)  asm volatile("cp.async.wait_group %0;" :: "n"(n) : "memory")

#define MMA8(c, a, b) \
    asm volatile("mma.sync.aligned.m16n8k8.row.col.f32.tf32.tf32.f32 " \
        "{%0,%1,%2,%3},{%4,%5,%6,%7},{%8,%9},{%0,%1,%2,%3};" \
        : "+f"((c)[0]), "+f"((c)[1]), "+f"((c)[2]), "+f"((c)[3]) \
        : "r"((a)[0]), "r"((a)[1]), "r"((a)[2]), "r"((a)[3]), \
          "r"((b)[0]), "r"((b)[1]))

// ---------------- keep mask ----------------
__global__ void k_zero_keep() {
    int i = blockIdx.x * blockDim.x + threadIdx.x;
    if (i < NN) d_keep[i] = 0;
}
__global__ void k_scatter(const int* __restrict__ stops) {
    int i = blockIdx.x * blockDim.x + threadIdx.x;
    if (i < NSTOP) d_keep[stops[i]] = 1;
}

// ---------------- row-normalize embeddings ----------------
__global__ void k_norm(const float* __restrict__ emb) {
    int i = blockIdx.x;
    int t = threadIdx.x;                 // 64
    float v = emb[i * DD + t];
    float s = v * v;
    #pragma unroll
    for (int o = 16; o; o >>= 1) s += __shfl_down_sync(0xffffffffu, s, o);
    __shared__ float ws[2];
    if ((t & 31) == 0) ws[t >> 5] = s;
    __syncthreads();
    float norm = fmaxf(sqrtf(ws[0] + ws[1]), 1e-8f);
    d_xn[i * DD + t] = v / norm;
}

// ---------------- adjacency row + mean aggregation, fused ----------------
__global__ void k_agg(const float* __restrict__ emb) {
    int i = blockIdx.x;
    int t = threadIdx.x;                 // 256
    if (!d_keep[i]) {
        if (t < DD) d_aggn[i * DD + t] = 0.f;
        return;
    }
    __shared__ __align__(16) float xi[DD];
    __shared__ unsigned mw[NN / 32];
    __shared__ int degs;
    __shared__ float aggp[256];

    if (t < DD) xi[t] = d_xn[i * DD + t];
    for (int w = t; w < NN / 32; w += 256) mw[w] = 0u;
    if (t == 0) degs = 0;
    __syncthreads();

    int cnt = 0;
    const float4* xi4 = (const float4*)xi;
    for (int j = t; j < NN; j += 256) {
        if (j == i || !d_keep[j]) continue;
        const float4* xj = (const float4*)(d_xn + j * DD);
        float s = 0.f;
        #pragma unroll
        for (int q = 0; q < DD / 4; q++) {
            float4 a = xj[q], b = xi4[q];
            s += a.x * b.x + a.y * b.y + a.z * b.z + a.w * b.w;
        }
        if (s > 0.5f) { atomicOr(&mw[j >> 5], 1u << (j & 31)); cnt++; }
    }
    if (cnt) atomicAdd(&degs, cnt);
    __syncthreads();

    float deg = fmaxf((float)degs, 1.0f);
    int d = t & (DD - 1);
    int g = t >> 6;
    float p = 0.f;
    for (int j = g; j < NN; j += 4) {
        if ((mw[j >> 5] >> (j & 31)) & 1u) p += emb[j * DD + d];
    }
    aggp[t] = p;
    __syncthreads();
    if (t < DD) {
        float s = aggp[t] + aggp[t + 64] + aggp[t + 128] + aggp[t + 192];
        d_aggn[i * DD + t] = s / deg;
    }
}

// ---------------- pref + edge vectors ----------------
__global__ void k_pref(const float* __restrict__ emb,
                       const float* __restrict__ llw, const float* __restrict__ llb,
                       const float* __restrict__ lrw, const float* __restrict__ ew) {
    int i = blockIdx.x;
    int p = threadIdx.x;                 // 32
    float s = llb[p];
    const float* ai = d_aggn + i * DD;
    const float* ei = emb + i * DD;
    #pragma unroll
    for (int d = 0; d < DD; d++)
        s += ai[d] * llw[p * DD + d] + ei[d] * lrw[p * DD + d];
    d_pref[i * PP + p] = s;
    float a = s * ew[p];
    float b = s * ew[PP + p];
    #pragma unroll
    for (int o = 16; o; o >>= 1) {
        a += __shfl_down_sync(0xffffffffu, a, o);
        b += __shfl_down_sync(0xffffffffu, b, o);
    }
    if (p == 0) { d_av[i] = a; d_bv[i] = b; }
}

// ---------------- combined value at (i,k) ----------------
__device__ __forceinline__ float comb_val(int i, int k, const float* __restrict__ dist,
                                          float eb, float wkf, float vhf) {
    if (k < PP) return d_pref[i * PP + k];
    if (k < PP + NN) {
        float e = d_av[i] + d_bv[k - PP] + eb;
        return (e >= 0.f) ? e : 0.01f * e;
    }
    if (k < PP + 2 * NN) return dist[(size_t)i * NN + (k - PP - NN)];
    if (k == PP + 2 * NN) return wkf;
    if (k == PP + 2 * NN + 1) return vhf;
    if (k == PP + 2 * NN + 2) return d_keep[i] ? 1.f : 0.f;
    return 0.f;
}

// A pack: per (m-tile, k-chunk) 128x32 block stored in m16n8k8 A-fragment order.
// atom (ki 0..3, mi 0..7) -> 128 floats: thread t=(g*4+tg) holds regs a0..a3.
__global__ void k_fill_a(const float* __restrict__ dist, const float* __restrict__ edge_b,
                         const int* __restrict__ wk, const int* __restrict__ vh) {
    int idx = blockIdx.x * blockDim.x + threadIdx.x;
    if (idx >= NN * KPAD) return;
    int i = idx / KPAD;
    int k = idx - i * KPAD;
    float v = comb_val(i, k, dist, edge_b[0], (float)wk[0], (float)vh[0]);
    int mt = i >> 7, r = i & 127, kc = k >> 5, kk = k & 31;
    int mi = r >> 4, rr = r & 15, g = rr & 7, hi = rr >> 3;
    int ki = kk >> 3, kki = kk & 7, tg = kki & 3, khi = kki >> 2;
    size_t off = (size_t)(mt * NCHUNK + kc) * TILE_FLOATS
               + (ki * 8 + mi) * 128 + (g * 4 + tg) * 4 + hi + 2 * khi;
    d_apack[off] = f2tf32(v);
}

// B pack: per (n-tile, k-chunk) 128x32 block in m16n8k8 B-fragment order.
// atom (ki 0..3, ni 0..15) -> 64 floats: thread t=(n*4+tg) holds b0,b1.
__global__ void k_fill_b(const float* __restrict__ combw) {
    int idx = blockIdx.x * blockDim.x + threadIdx.x;
    if (idx >= NN * KPAD) return;
    int i = idx / KPAD;                  // weight row = output column
    int k = idx - i * KPAD;
    float v = (k < KIN) ? combw[(size_t)i * KIN + k] : 0.f;
    int nt = i >> 7, r = i & 127, kc = k >> 5, kk = k & 31;
    int ni = r >> 3, rn = r & 7;
    int ki = kk >> 3, kki = kk & 7, tg = kki & 3, reg = kki >> 2;
    size_t off = (size_t)(nt * NCHUNK + kc) * TILE_FLOATS
               + (ki * 16 + ni) * 64 + (rn * 4 + tg) * 2 + reg;
    d_bpack[off] = f2tf32(v);
}

// ---------------- stage loader ----------------
__device__ __forceinline__ void load_stage(uint32_t sbase, int s,
                                           const uint32_t* aP, const uint32_t* bP, int tid) {
    uint32_t dst = sbase + s * (STAGE_FLOATS * 4) + tid * 16;
    const uint32_t* a = aP + tid * 4;
    #pragma unroll
    for (int j = 0; j < 4; j++) CP_ASYNC16(dst + j * 4096, a + j * 1024);
    dst += TILE_FLOATS * 4;
    const uint32_t* b = bP + tid * 4;
    #pragma unroll
    for (int j = 0; j < 4; j++) CP_ASYNC16(dst + j * 4096, b + j * 1024);
}

// ---------------- tf32 mma GEMM: C[128x128] per CTA ----------------
__global__ __launch_bounds__(256, 2) void k_gemm_mma(const float* __restrict__ bias,
                                                     float* __restrict__ C) {
    extern __shared__ __align__(16) float sm[];
    int tid = threadIdx.x, lane = tid & 31, wid = tid >> 5;
    int warpM = wid & 3, warpN = wid >> 2;      // 4 x 2
    int mt = blockIdx.y, nt = blockIdx.x;
    const uint32_t* aP0 = d_apack + (size_t)mt * NCHUNK * TILE_FLOATS;
    const uint32_t* bP0 = d_bpack + (size_t)nt * NCHUNK * TILE_FLOATS;
    uint32_t sbase = smem_u32(sm);

    float acc[2][8][4];
    #pragma unroll
    for (int m = 0; m < 2; m++)
        #pragma unroll
        for (int n = 0; n < 8; n++)
            #pragma unroll
            for (int q = 0; q < 4; q++) acc[m][n][q] = 0.f;

    #pragma unroll
    for (int p = 0; p < NSTG - 1; p++) {
        load_stage(sbase, p, aP0 + (size_t)p * TILE_FLOATS, bP0 + (size_t)p * TILE_FLOATS, tid);
        CP_COMMIT();
    }

    for (int kc = 0; kc < NCHUNK; kc++) {
        CP_WAIT(NSTG - 2);
        __syncthreads();
        int pf = kc + NSTG - 1;
        if (pf < NCHUNK)
            load_stage(sbase, pf % NSTG, aP0 + (size_t)pf * TILE_FLOATS,
                       bP0 + (size_t)pf * TILE_FLOATS, tid);
        CP_COMMIT();

        const float* As = sm + (kc % NSTG) * STAGE_FLOATS;
        const float* Bs = As + TILE_FLOATS;
        #pragma unroll
        for (int ki = 0; ki < 4; ki++) {
            uint32_t af[2][4];
            #pragma unroll
            for (int m = 0; m < 2; m++) {
                float4 v = *(const float4*)(As + ((ki * 8 + warpM * 2 + m) * 128 + lane * 4));
                af[m][0] = __float_as_uint(v.x); af[m][1] = __float_as_uint(v.y);
                af[m][2] = __float_as_uint(v.z); af[m][3] = __float_as_uint(v.w);
            }
            uint32_t bf[8][2];
            #pragma unroll
            for (int n = 0; n < 8; n++) {
                float2 w = *(const float2*)(Bs + ((ki * 16 + warpN * 8 + n) * 64 + lane * 2));
                bf[n][0] = __float_as_uint(w.x); bf[n][1] = __float_as_uint(w.y);
            }
            #pragma unroll
            for (int m = 0; m < 2; m++)
                #pragma unroll
                for (int n = 0; n < 8; n++) MMA8(acc[m][n], af[m], bf[n]);
        }
    }

    // epilogue
    int g = lane >> 2, tg = lane & 3;
    int rowBase = mt * BM + warpM * 32;
    int colBase = nt * BN + warpN * 64;
    #pragma unroll
    for (int m = 0; m < 2; m++) {
        int r0 = rowBase + m * 16 + g;
        #pragma unroll
        for (int n = 0; n < 8; n++) {
            int c = colBase + n * 8 + tg * 2;
            float2 bb = *(const float2*)(bias + c);
            float2 o0 = { acc[m][n][0] + bb.x, acc[m][n][1] + bb.y };
            float2 o1 = { acc[m][n][2] + bb.x, acc[m][n][3] + bb.y };
            *(float2*)(C + (size_t)r0 * NN + c) = o0;
            *(float2*)(C + (size_t)(r0 + 8) * NN + c) = o1;
        }
    }
}

// ---------------- in-place row log-softmax ----------------
__global__ void k_lsm(float* __restrict__ out) {
    int i = blockIdx.x;
    int t = threadIdx.x;                 // 256
    __shared__ float row[NN];
    __shared__ float red[256];

    float m = -1e30f;
    for (int j = t; j < NN; j += 256) {
        float v = out[(size_t)i * NN + j];
        row[j] = v;
        m = fmaxf(m, v);
    }
    red[t] = m;
    __syncthreads();
    #pragma unroll
    for (int o = 128; o; o >>= 1) {
        if (t < o) red[t] = fmaxf(red[t], red[t + o]);
        __syncthreads();
    }
    float mx = red[0];
    __syncthreads();

    float s = 0.f;
    for (int j = t; j < NN; j += 256) s += expf(row[j] - mx);
    red[t] = s;
    __syncthreads();
    #pragma unroll
    for (int o = 128; o; o >>= 1) {
        if (t < o) red[t] += red[t + o];
        __syncthreads();
    }
    float lse = logf(red[0]) + mx;

    for (int j = t; j < NN; j += 256) out[(size_t)i * NN + j] = row[j] - lse;
}

// ---------------- launch ----------------
extern "C" void kernel_launch(void* const* d_in, const int* in_sizes, int n_in,
                              void* d_out, int out_size) {
    const float* dist   = (const float*)d_in[0];
    const float* emb    = (const float*)d_in[1];
    const float* llw    = (const float*)d_in[2];
    const float* llb    = (const float*)d_in[3];
    const float* lrw    = (const float*)d_in[4];
    const float* ew     = (const float*)d_in[5];
    const float* edge_b = (const float*)d_in[6];
    const float* combw  = (const float*)d_in[7];
    const float* combb  = (const float*)d_in[8];
    const int*   stops  = (const int*)d_in[9];
    const int*   wk     = (const int*)d_in[10];
    const int*   vh     = (const int*)d_in[11];
    float* out = (float*)d_out;

    k_zero_keep<<<(NN + 255) / 256, 256>>>();
    k_scatter<<<(NSTOP + 255) / 256, 256>>>(stops);
    k_norm<<<NN, DD>>>(emb);
    k_agg<<<NN, 256>>>(emb);
    k_pref<<<NN, PP>>>(emb, llw, llb, lrw, ew);

    int tot = NN * KPAD;
    k_fill_a<<<(tot + 255) / 256, 256>>>(dist, edge_b, wk, vh);
    k_fill_b<<<(tot + 255) / 256, 256>>>(combw);

    cudaFuncSetAttribute(k_gemm_mma, cudaFuncAttributeMaxDynamicSharedMemorySize, GEMM_SMEM);
    dim3 gg(NN / BN, NN / BM);
    k_gemm_mma<<<gg, 256, GEMM_SMEM>>>(combb, out);

    k_lsm<<<NN, 256>>>(out);
}

// round 4
// speedup vs baseline: 3.1663x; 1.0016x over previous
#include <cuda_runtime.h>
#include <math.h>
#include <stdint.h>

#define NN 2048
#define DD 64
#define PP 32
#define NSTOP 512
#define KIN 4131          // 2*N + 3 + P
#define KPAD 4160         // 130 chunks of 32
#define NCHUNK 130
#define BM 128
#define BN 128
#define BK 32
#define NSTG 3
#define TILE_FLOATS 4096          // BM*BK == BN*BK
#define STAGE_FLOATS 8192
#define GEMM_SMEM (NSTG * STAGE_FLOATS * 4)

// ---------------- scratch (device globals: allocation-free) ----------------
__device__ __align__(16) float d_xn[NN * DD];
__device__ int   d_keep[NN];
__device__ __align__(16) float d_aggn[NN * DD];
__device__ float d_pref[NN * PP];
__device__ float d_av[NN];
__device__ float d_bv[NN];
// operands pre-packed in mma-fragment order, tf32-converted
__device__ __align__(128) uint32_t d_apack[(size_t)NN * KPAD];
__device__ __align__(128) uint32_t d_bpack[(size_t)NN * KPAD];

// ---------------- helpers ----------------
__device__ __forceinline__ uint32_t smem_u32(const void* p) {
    uint32_t a;
    asm("{ .reg .u64 t; cvta.to.shared.u64 t, %1; cvt.u32.u64 %0, t; }" : "=r"(a) : "l"(p));
    return a;
}
__device__ __forceinline__ uint32_t f2tf32(float f) {
    uint32_t r;
    asm("cvt.rna.tf32.f32 %0, %1;" : "=r"(r) : "f"(f));
    return r;
}
#define CP_ASYNC16(dst, src) \
    asm volatile("cp.async.cg.shared.global [%0], [%1], 16;" :: "r"(dst), "l"(src) : "memory")
#define CP_COMMIT() asm volatile("cp.async.commit_group;" ::: "memory")
#define CP_WAIT(n)  asm volatile("cp.async.wait_group %0;" :: "n"(n) : "memory")

#define MMA8(c, a, b) \
    asm volatile("mma.sync.aligned.m16n8k8.row.col.f32.tf32.tf32.f32 " \
        "{%0,%1,%2,%3},{%4,%5,%6,%7},{%8,%9},{%0,%1,%2,%3};" \
        : "+f"((c)[0]), "+f"((c)[1]), "+f"((c)[2]), "+f"((c)[3]) \
        : "r"((a)[0]), "r"((a)[1]), "r"((a)[2]), "r"((a)[3]), \
          "r"((b)[0]), "r"((b)[1]))

// ---------------- keep mask ----------------
__global__ void k_zero_keep() {
    int i = blockIdx.x * blockDim.x + threadIdx.x;
    if (i < NN) d_keep[i] = 0;
}
__global__ void k_scatter(const int* __restrict__ stops) {
    int i = blockIdx.x * blockDim.x + threadIdx.x;
    if (i < NSTOP) d_keep[stops[i]] = 1;
}

// ---------------- row-normalize embeddings ----------------
__global__ void k_norm(const float* __restrict__ emb) {
    int i = blockIdx.x;
    int t = threadIdx.x;                 // 64
    float v = emb[i * DD + t];
    float s = v * v;
    #pragma unroll
    for (int o = 16; o; o >>= 1) s += __shfl_down_sync(0xffffffffu, s, o);
    __shared__ float ws[2];
    if ((t & 31) == 0) ws[t >> 5] = s;
    __syncthreads();
    float norm = fmaxf(sqrtf(ws[0] + ws[1]), 1e-8f);
    d_xn[i * DD + t] = v / norm;
}

// ---------------- adjacency row + mean aggregation, fused ----------------
__global__ void k_agg(const float* __restrict__ emb) {
    int i = blockIdx.x;
    int t = threadIdx.x;                 // 256
    if (!d_keep[i]) {
        if (t < DD) d_aggn[i * DD + t] = 0.f;
        return;
    }
    __shared__ __align__(16) float xi[DD];
    __shared__ unsigned mw[NN / 32];
    __shared__ int degs;
    __shared__ float aggp[256];

    if (t < DD) xi[t] = d_xn[i * DD + t];
    for (int w = t; w < NN / 32; w += 256) mw[w] = 0u;
    if (t == 0) degs = 0;
    __syncthreads();

    int cnt = 0;
    const float4* xi4 = (const float4*)xi;
    for (int j = t; j < NN; j += 256) {
        if (j == i || !d_keep[j]) continue;
        const float4* xj = (const float4*)(d_xn + j * DD);
        float s = 0.f;
        #pragma unroll
        for (int q = 0; q < DD / 4; q++) {
            float4 a = xj[q], b = xi4[q];
            s += a.x * b.x + a.y * b.y + a.z * b.z + a.w * b.w;
        }
        if (s > 0.5f) { atomicOr(&mw[j >> 5], 1u << (j & 31)); cnt++; }
    }
    if (cnt) atomicAdd(&degs, cnt);
    __syncthreads();

    float deg = fmaxf((float)degs, 1.0f);
    int d = t & (DD - 1);
    int g = t >> 6;
    float p = 0.f;
    for (int j = g; j < NN; j += 4) {
        if ((mw[j >> 5] >> (j & 31)) & 1u) p += emb[j * DD + d];
    }
    aggp[t] = p;
    __syncthreads();
    if (t < DD) {
        float s = aggp[t] + aggp[t + 64] + aggp[t + 128] + aggp[t + 192];
        d_aggn[i * DD + t] = s / deg;
    }
}

// ---------------- pref + edge vectors ----------------
__global__ void k_pref(const float* __restrict__ emb,
                       const float* __restrict__ llw, const float* __restrict__ llb,
                       const float* __restrict__ lrw, const float* __restrict__ ew) {
    int i = blockIdx.x;
    int p = threadIdx.x;                 // 32
    float s = llb[p];
    const float* ai = d_aggn + i * DD;
    const float* ei = emb + i * DD;
    #pragma unroll
    for (int d = 0; d < DD; d++)
        s += ai[d] * llw[p * DD + d] + ei[d] * lrw[p * DD + d];
    d_pref[i * PP + p] = s;
    float a = s * ew[p];
    float b = s * ew[PP + p];
    #pragma unroll
    for (int o = 16; o; o >>= 1) {
        a += __shfl_down_sync(0xffffffffu, a, o);
        b += __shfl_down_sync(0xffffffffu, b, o);
    }
    if (p == 0) { d_av[i] = a; d_bv[i] = b; }
}

// ---------------- combined value at (i,k) ----------------
__device__ __forceinline__ float comb_val(int i, int k, const float* __restrict__ dist,
                                          float eb, float wkf, float vhf) {
    if (k < PP) return d_pref[i * PP + k];
    if (k < PP + NN) {
        float e = d_av[i] + d_bv[k - PP] + eb;
        return (e >= 0.f) ? e : 0.01f * e;
    }
    if (k < PP + 2 * NN) return dist[(size_t)i * NN + (k - PP - NN)];
    if (k == PP + 2 * NN) return wkf;
    if (k == PP + 2 * NN + 1) return vhf;
    if (k == PP + 2 * NN + 2) return d_keep[i] ? 1.f : 0.f;
    return 0.f;
}

// A pack: per (m-tile, k-chunk) 128x32 block stored in m16n8k8 A-fragment order.
// atom (ki 0..3, mi 0..7) -> 128 floats: thread t=(g*4+tg) holds regs a0..a3.
__global__ void k_fill_a(const float* __restrict__ dist, const float* __restrict__ edge_b,
                         const int* __restrict__ wk, const int* __restrict__ vh) {
    int idx = blockIdx.x * blockDim.x + threadIdx.x;
    if (idx >= NN * KPAD) return;
    int i = idx / KPAD;
    int k = idx - i * KPAD;
    float v = comb_val(i, k, dist, edge_b[0], (float)wk[0], (float)vh[0]);
    int mt = i >> 7, r = i & 127, kc = k >> 5, kk = k & 31;
    int mi = r >> 4, rr = r & 15, g = rr & 7, hi = rr >> 3;
    int ki = kk >> 3, kki = kk & 7, tg = kki & 3, khi = kki >> 2;
    size_t off = (size_t)(mt * NCHUNK + kc) * TILE_FLOATS
               + (ki * 8 + mi) * 128 + (g * 4 + tg) * 4 + hi + 2 * khi;
    d_apack[off] = f2tf32(v);
}

// B pack: per (n-tile, k-chunk) 128x32 block in m16n8k8 B-fragment order.
// atom (ki 0..3, ni 0..15) -> 64 floats: thread t=(n*4+tg) holds b0,b1.
__global__ void k_fill_b(const float* __restrict__ combw) {
    int idx = blockIdx.x * blockDim.x + threadIdx.x;
    if (idx >= NN * KPAD) return;
    int i = idx / KPAD;                  // weight row = output column
    int k = idx - i * KPAD;
    float v = (k < KIN) ? combw[(size_t)i * KIN + k] : 0.f;
    int nt = i >> 7, r = i & 127, kc = k >> 5, kk = k & 31;
    int ni = r >> 3, rn = r & 7;
    int ki = kk >> 3, kki = kk & 7, tg = kki & 3, reg = kki >> 2;
    size_t off = (size_t)(nt * NCHUNK + kc) * TILE_FLOATS
               + (ki * 16 + ni) * 64 + (rn * 4 + tg) * 2 + reg;
    d_bpack[off] = f2tf32(v);
}

// ---------------- stage loader ----------------
__device__ __forceinline__ void load_stage(uint32_t sbase, int s,
                                           const uint32_t* aP, const uint32_t* bP, int tid) {
    uint32_t dst = sbase + s * (STAGE_FLOATS * 4) + tid * 16;
    const uint32_t* a = aP + tid * 4;
    #pragma unroll
    for (int j = 0; j < 4; j++) CP_ASYNC16(dst + j * 4096, a + j * 1024);
    dst += TILE_FLOATS * 4;
    const uint32_t* b = bP + tid * 4;
    #pragma unroll
    for (int j = 0; j < 4; j++) CP_ASYNC16(dst + j * 4096, b + j * 1024);
}

// ---------------- tf32 mma GEMM: C[128x128] per CTA ----------------
__global__ __launch_bounds__(256, 2) void k_gemm_mma(const float* __restrict__ bias,
                                                     float* __restrict__ C) {
    extern __shared__ __align__(16) float sm[];
    int tid = threadIdx.x, lane = tid & 31, wid = tid >> 5;
    int warpM = wid & 3, warpN = wid >> 2;      // 4 x 2
    int mt = blockIdx.y, nt = blockIdx.x;
    const uint32_t* aP0 = d_apack + (size_t)mt * NCHUNK * TILE_FLOATS;
    const uint32_t* bP0 = d_bpack + (size_t)nt * NCHUNK * TILE_FLOATS;
    uint32_t sbase = smem_u32(sm);

    float acc[2][8][4];
    #pragma unroll
    for (int m = 0; m < 2; m++)
        #pragma unroll
        for (int n = 0; n < 8; n++)
            #pragma unroll
            for (int q = 0; q < 4; q++) acc[m][n][q] = 0.f;

    #pragma unroll
    for (int p = 0; p < NSTG - 1; p++) {
        load_stage(sbase, p, aP0 + (size_t)p * TILE_FLOATS, bP0 + (size_t)p * TILE_FLOATS, tid);
        CP_COMMIT();
    }

    for (int kc = 0; kc < NCHUNK; kc++) {
        CP_WAIT(NSTG - 2);
        __syncthreads();
        int pf = kc + NSTG - 1;
        if (pf < NCHUNK)
            load_stage(sbase, pf % NSTG, aP0 + (size_t)pf * TILE_FLOATS,
                       bP0 + (size_t)pf * TILE_FLOATS, tid);
        CP_COMMIT();

        const float* As = sm + (kc % NSTG) * STAGE_FLOATS;
        const float* Bs = As + TILE_FLOATS;
        #pragma unroll
        for (int ki = 0; ki < 4; ki++) {
            uint32_t af[2][4];
            #pragma unroll
            for (int m = 0; m < 2; m++) {
                float4 v = *(const float4*)(As + ((ki * 8 + warpM * 2 + m) * 128 + lane * 4));
                af[m][0] = __float_as_uint(v.x); af[m][1] = __float_as_uint(v.y);
                af[m][2] = __float_as_uint(v.z); af[m][3] = __float_as_uint(v.w);
            }
            uint32_t bf[8][2];
            #pragma unroll
            for (int n = 0; n < 8; n++) {
                float2 w = *(const float2*)(Bs + ((ki * 16 + warpN * 8 + n) * 64 + lane * 2));
                bf[n][0] = __float_as_uint(w.x); bf[n][1] = __float_as_uint(w.y);
            }
            #pragma unroll
            for (int m = 0; m < 2; m++)
                #pragma unroll
                for (int n = 0; n < 8; n++) MMA8(acc[m][n], af[m], bf[n]);
        }
    }

    // epilogue
    int g = lane >> 2, tg = lane & 3;
    int rowBase = mt * BM + warpM * 32;
    int colBase = nt * BN + warpN * 64;
    #pragma unroll
    for (int m = 0; m < 2; m++) {
        int r0 = rowBase + m * 16 + g;
        #pragma unroll
        for (int n = 0; n < 8; n++) {
            int c = colBase + n * 8 + tg * 2;
            float2 bb = *(const float2*)(bias + c);
            float2 o0 = { acc[m][n][0] + bb.x, acc[m][n][1] + bb.y };
            float2 o1 = { acc[m][n][2] + bb.x, acc[m][n][3] + bb.y };
            *(float2*)(C + (size_t)r0 * NN + c) = o0;
            *(float2*)(C + (size_t)(r0 + 8) * NN + c) = o1;
        }
    }
}

// ---------------- in-place row log-softmax ----------------
__global__ void k_lsm(float* __restrict__ out) {
    int i = blockIdx.x;
    int t = threadIdx.x;                 // 256
    __shared__ float row[NN];
    __shared__ float red[256];

    float m = -1e30f;
    for (int j = t; j < NN; j += 256) {
        float v = out[(size_t)i * NN + j];
        row[j] = v;
        m = fmaxf(m, v);
    }
    red[t] = m;
    __syncthreads();
    #pragma unroll
    for (int o = 128; o; o >>= 1) {
        if (t < o) red[t] = fmaxf(red[t], red[t + o]);
        __syncthreads();
    }
    float mx = red[0];
    __syncthreads();

    float s = 0.f;
    for (int j = t; j < NN; j += 256) s += expf(row[j] - mx);
    red[t] = s;
    __syncthreads();
    #pragma unroll
    for (int o = 128; o; o >>= 1) {
        if (t < o) red[t] += red[t + o];
        __syncthreads();
    }
    float lse = logf(red[0]) + mx;

    for (int j = t; j < NN; j += 256) out[(size_t)i * NN + j] = row[j] - lse;
}

// ---------------- launch ----------------
extern "C" void kernel_launch(void* const* d_in, const int* in_sizes, int n_in,
                              void* d_out, int out_size) {
    const float* dist   = (const float*)d_in[0];
    const float* emb    = (const float*)d_in[1];
    const float* llw    = (const float*)d_in[2];
    const float* llb    = (const float*)d_in[3];
    const float* lrw    = (const float*)d_in[4];
    const float* ew     = (const float*)d_in[5];
    const float* edge_b = (const float*)d_in[6];
    const float* combw  = (const float*)d_in[7];
    const float* combb  = (const float*)d_in[8];
    const int*   stops  = (const int*)d_in[9];
    const int*   wk     = (const int*)d_in[10];
    const int*   vh     = (const int*)d_in[11];
    float* out = (float*)d_out;

    k_zero_keep<<<(NN + 255) / 256, 256>>>();
    k_scatter<<<(NSTOP + 255) / 256, 256>>>(stops);
    k_norm<<<NN, DD>>>(emb);
    k_agg<<<NN, 256>>>(emb);
    k_pref<<<NN, PP>>>(emb, llw, llb, lrw, ew);

    int tot = NN * KPAD;
    k_fill_a<<<(tot + 255) / 256, 256>>>(dist, edge_b, wk, vh);
    k_fill_b<<<(tot + 255) / 256, 256>>>(combw);

    cudaFuncSetAttribute(k_gemm_mma, cudaFuncAttributeMaxDynamicSharedMemorySize, GEMM_SMEM);
    dim3 gg(NN / BN, NN / BM);
    k_gemm_mma<<<gg, 256, GEMM_SMEM>>>(combb, out);

    k_lsm<<<NN, 256>>>(out);
}

// round 5
// speedup vs baseline: 5.1444x; 1.6247x over previous
#include <cuda_runtime.h>
#include <cuda_bf16.h>
#include <math.h>
#include <stdint.h>

#define NN 2048
#define DD 64
#define PP 32
#define NSTOP 512
#define KIN 4131          // 2*N + 3 + P
#define KPAD 4160         // 130 chunks of 32
#define NCHUNK 130
#define BM 128
#define BN 128
#define NSTG 4
#define TILE_U32 2048             // 128x32 bf16 = 2048 uint32
#define STAGE_U32 4096
#define STAGE_B 16384
#define GEMM_SMEM (NSTG * STAGE_B)

// ---------------- scratch (device globals: allocation-free) ----------------
__device__ unsigned d_kmask[NN / 32];
__device__ int   d_klist[NSTOP];
__device__ __align__(16) float d_xn[NN * DD];
__device__ __align__(16) float d_xnc[NSTOP * DD];   // compacted normalized rows
__device__ __align__(16) float d_embc[NSTOP * DD];  // compacted raw emb rows
__device__ __align__(16) float d_aggn[NN * DD];
__device__ float d_pref[NN * PP];
__device__ float d_av[NN];
__device__ float d_bv[NN];
// operands pre-packed in m16n8k16 bf16 fragment order
__device__ __align__(128) uint32_t d_apack[(size_t)NN * KPAD / 2];
__device__ __align__(128) uint32_t d_bpack[(size_t)NN * KPAD / 2];

// ---------------- helpers ----------------
__device__ __forceinline__ uint32_t smem_u32(const void* p) {
    uint32_t a;
    asm("{ .reg .u64 t; cvta.to.shared.u64 t, %1; cvt.u32.u64 %0, t; }" : "=r"(a) : "l"(p));
    return a;
}
__device__ __forceinline__ uint32_t pack_bf16(float a, float b) {
    __nv_bfloat162 h = __floats2bfloat162_rn(a, b);
    return *(uint32_t*)&h;
}
#define CP_ASYNC16(dst, src) \
    asm volatile("cp.async.cg.shared.global [%0], [%1], 16;" :: "r"(dst), "l"(src) : "memory")
#define CP_COMMIT() asm volatile("cp.async.commit_group;" ::: "memory")
#define CP_WAIT(n)  asm volatile("cp.async.wait_group %0;" :: "n"(n) : "memory")

#define MMA16(c, a, b) \
    asm volatile("mma.sync.aligned.m16n8k16.row.col.f32.bf16.bf16.f32 " \
        "{%0,%1,%2,%3},{%4,%5,%6,%7},{%8,%9},{%0,%1,%2,%3};" \
        : "+f"((c)[0]), "+f"((c)[1]), "+f"((c)[2]), "+f"((c)[3]) \
        : "r"((a)[0]), "r"((a)[1]), "r"((a)[2]), "r"((a)[3]), \
          "r"((b)[0]), "r"((b)[1]))

__device__ __forceinline__ int keep_bit(int i) {
    return (d_kmask[i >> 5] >> (i & 31)) & 1;
}

// ---------------- init: zero mask + zero agg ----------------
__global__ void k_zero() {
    int i = blockIdx.x * blockDim.x + threadIdx.x;
    if (i < NN * DD) d_aggn[i] = 0.f;
    if (i < NN / 32) d_kmask[i] = 0u;
}
__global__ void k_scatter(const int* __restrict__ stops) {
    int i = blockIdx.x * blockDim.x + threadIdx.x;
    if (i < NSTOP) {
        int s = stops[i];
        atomicOr(&d_kmask[s >> 5], 1u << (s & 31));
    }
}

// ---------------- row-normalize embeddings ----------------
__global__ void k_norm(const float* __restrict__ emb) {
    int i = blockIdx.x;
    int t = threadIdx.x;                 // 64
    float v = emb[i * DD + t];
    float s = v * v;
    #pragma unroll
    for (int o = 16; o; o >>= 1) s += __shfl_down_sync(0xffffffffu, s, o);
    __shared__ float ws[2];
    if ((t & 31) == 0) ws[t >> 5] = s;
    __syncthreads();
    float norm = fmaxf(sqrtf(ws[0] + ws[1]), 1e-8f);
    d_xn[i * DD + t] = v / norm;
}

// ---------------- deterministic compaction of kept rows ----------------
__global__ void k_compact(const float* __restrict__ emb) {   // grid NN, block 64
    int i = blockIdx.x, t = threadIdx.x;
    unsigned w = d_kmask[i >> 5];
    if (!((w >> (i & 31)) & 1)) return;
    __shared__ int spos;
    if (t == 0) {
        int pos = 0;
        for (int q = 0; q < (i >> 5); q++) pos += __popc(d_kmask[q]);
        pos += __popc(w & ((1u << (i & 31)) - 1u));
        spos = pos;
        d_klist[pos] = i;
    }
    __syncthreads();
    int pos = spos;
    d_xnc[pos * DD + t] = d_xn[i * DD + t];
    d_embc[pos * DD + t] = emb[i * DD + t];
}

// ---------------- agg over compacted kept set ----------------
__global__ void k_agg2() {                                   // grid NSTOP, block 256
    int b = blockIdx.x, t = threadIdx.x;
    __shared__ int snk;
    __shared__ __align__(16) float xi[DD];
    __shared__ unsigned mw[NSTOP / 32];
    __shared__ int degs;
    __shared__ float aggp[256];
    if (t == 0) { snk = 0; degs = 0; }
    if (t < NSTOP / 32) mw[t] = 0u;
    __syncthreads();
    if (t < NN / 32) atomicAdd(&snk, __popc(d_kmask[t]));
    __syncthreads();
    int nk = snk;
    if (b >= nk) return;
    if (t < DD) xi[t] = d_xnc[b * DD + t];
    __syncthreads();

    int cnt = 0;
    const float4* xi4 = (const float4*)xi;
    for (int j = t; j < nk; j += 256) {
        if (j == b) continue;
        const float4* xj = (const float4*)(d_xnc + j * DD);
        float s = 0.f;
        #pragma unroll
        for (int q = 0; q < DD / 4; q++) {
            float4 a = xj[q], bb = xi4[q];
            s += a.x * bb.x + a.y * bb.y + a.z * bb.z + a.w * bb.w;
        }
        if (s > 0.5f) { atomicOr(&mw[j >> 5], 1u << (j & 31)); cnt++; }
    }
    if (cnt) atomicAdd(&degs, cnt);
    __syncthreads();

    float deg = fmaxf((float)degs, 1.0f);
    int d = t & (DD - 1);
    int g = t >> 6;
    float p = 0.f;
    for (int j = g; j < nk; j += 4) {
        if ((mw[j >> 5] >> (j & 31)) & 1u) p += d_embc[j * DD + d];
    }
    aggp[t] = p;
    __syncthreads();
    if (t < DD) {
        float s = aggp[t] + aggp[t + 64] + aggp[t + 128] + aggp[t + 192];
        d_aggn[d_klist[b] * DD + t] = s / deg;
    }
}

// ---------------- pref + edge vectors ----------------
__global__ void k_pref(const float* __restrict__ emb,
                       const float* __restrict__ llw, const float* __restrict__ llb,
                       const float* __restrict__ lrw, const float* __restrict__ ew) {
    int i = blockIdx.x;
    int p = threadIdx.x;                 // 32
    float s = llb[p];
    const float* ai = d_aggn + i * DD;
    const float* ei = emb + i * DD;
    #pragma unroll
    for (int d = 0; d < DD; d++)
        s += ai[d] * llw[p * DD + d] + ei[d] * lrw[p * DD + d];
    d_pref[i * PP + p] = s;
    float a = s * ew[p];
    float b = s * ew[PP + p];
    #pragma unroll
    for (int o = 16; o; o >>= 1) {
        a += __shfl_down_sync(0xffffffffu, a, o);
        b += __shfl_down_sync(0xffffffffu, b, o);
    }
    if (p == 0) { d_av[i] = a; d_bv[i] = b; }
}

// ---------------- combined value at (i,k) ----------------
__device__ __forceinline__ float comb_val(int i, int k, const float* __restrict__ dist,
                                          float eb, float wkf, float vhf) {
    if (k < PP) return d_pref[i * PP + k];
    if (k < PP + NN) {
        float e = d_av[i] + d_bv[k - PP] + eb;
        return (e >= 0.f) ? e : 0.01f * e;
    }
    if (k < PP + 2 * NN) return dist[(size_t)i * NN + (k - PP - NN)];
    if (k == PP + 2 * NN) return wkf;
    if (k == PP + 2 * NN + 1) return vhf;
    if (k == PP + 2 * NN + 2) return keep_bit(i) ? 1.f : 0.f;
    return 0.f;
}

// A pack: m16n8k16 A-fragment order, bf16 pairs.
__global__ void k_fill_a(const float* __restrict__ dist, const float* __restrict__ edge_b,
                         const int* __restrict__ wk, const int* __restrict__ vh) {
    int idx = blockIdx.x * blockDim.x + threadIdx.x;
    if (idx >= NN * (KPAD / 2)) return;
    int i = idx / (KPAD / 2);
    int k = (idx - i * (KPAD / 2)) * 2;
    float eb = edge_b[0], wkf = (float)wk[0], vhf = (float)vh[0];
    float v0 = comb_val(i, k, dist, eb, wkf, vhf);
    float v1 = comb_val(i, k + 1, dist, eb, wkf, vhf);
    int mt = i >> 7, r = i & 127, kc = k >> 5, kk = k & 31;
    int ki = kk >> 4, kkk = kk & 15;
    int mi = r >> 4, rr = r & 15, g = rr & 7, hi = rr >> 3;
    int sel = kkk >> 3, tg = (kkk & 7) >> 1;
    int reg = sel * 2 + hi;
    int lane = g * 4 + tg;
    size_t off = (size_t)(mt * NCHUNK + kc) * TILE_U32 + (ki * 8 + mi) * 128 + lane * 4 + reg;
    d_apack[off] = pack_bf16(v0, v1);
}

// B pack: m16n8k16 B-fragment order, bf16 pairs.
__global__ void k_fill_b(const float* __restrict__ combw) {
    int idx = blockIdx.x * blockDim.x + threadIdx.x;
    if (idx >= NN * (KPAD / 2)) return;
    int i = idx / (KPAD / 2);            // weight row = output column
    int k = (idx - i * (KPAD / 2)) * 2;
    const float* wrow = combw + (size_t)i * KIN;
    float v0 = (k + 0 < KIN) ? wrow[k + 0] : 0.f;
    float v1 = (k + 1 < KIN) ? wrow[k + 1] : 0.f;
    int nt = i >> 7, r = i & 127, kc = k >> 5, kk = k & 31;
    int ki = kk >> 4, kkk = kk & 15;
    int ni = r >> 3, gb = r & 7;
    int reg = kkk >> 3, tg = (kkk & 7) >> 1;
    int lane = gb * 4 + tg;
    size_t off = (size_t)(nt * NCHUNK + kc) * TILE_U32 + (ki * 16 + ni) * 64 + lane * 2 + reg;
    d_bpack[off] = pack_bf16(v0, v1);
}

// ---------------- stage loader: 16KB linear copy ----------------
__device__ __forceinline__ void load_stage(uint32_t sbase, int s,
                                           const uint32_t* aP, const uint32_t* bP, int tid) {
    uint32_t dst = sbase + s * STAGE_B + tid * 16;
    CP_ASYNC16(dst,          aP + tid * 4);
    CP_ASYNC16(dst + 4096,   aP + 1024 + tid * 4);
    CP_ASYNC16(dst + 8192,   bP + tid * 4);
    CP_ASYNC16(dst + 12288,  bP + 1024 + tid * 4);
}

// ---------------- bf16 mma GEMM: C[128x128] per CTA ----------------
__global__ __launch_bounds__(256, 2) void k_gemm_mma(const float* __restrict__ bias,
                                                     float* __restrict__ C) {
    extern __shared__ __align__(16) uint32_t smu[];
    int tid = threadIdx.x, lane = tid & 31, wid = tid >> 5;
    int warpM = wid & 3, warpN = wid >> 2;      // 4 x 2
    int mt = blockIdx.y, nt = blockIdx.x;
    const uint32_t* aP0 = d_apack + (size_t)mt * NCHUNK * TILE_U32;
    const uint32_t* bP0 = d_bpack + (size_t)nt * NCHUNK * TILE_U32;
    uint32_t sbase = smem_u32(smu);

    float acc[2][8][4];
    #pragma unroll
    for (int m = 0; m < 2; m++)
        #pragma unroll
        for (int n = 0; n < 8; n++)
            #pragma unroll
            for (int q = 0; q < 4; q++) acc[m][n][q] = 0.f;

    #pragma unroll
    for (int p = 0; p < NSTG - 1; p++) {
        load_stage(sbase, p, aP0 + (size_t)p * TILE_U32, bP0 + (size_t)p * TILE_U32, tid);
        CP_COMMIT();
    }

    for (int kc = 0; kc < NCHUNK; kc++) {
        CP_WAIT(NSTG - 2);
        __syncthreads();
        int pf = kc + NSTG - 1;
        if (pf < NCHUNK)
            load_stage(sbase, pf % NSTG, aP0 + (size_t)pf * TILE_U32,
                       bP0 + (size_t)pf * TILE_U32, tid);
        CP_COMMIT();

        const uint32_t* As = smu + (kc % NSTG) * STAGE_U32;
        const uint32_t* Bs = As + TILE_U32;
        #pragma unroll
        for (int ki = 0; ki < 2; ki++) {
            uint32_t af[2][4];
            #pragma unroll
            for (int m = 0; m < 2; m++) {
                uint4 v = *(const uint4*)(As + ((ki * 8 + warpM * 2 + m) * 128 + lane * 4));
                af[m][0] = v.x; af[m][1] = v.y; af[m][2] = v.z; af[m][3] = v.w;
            }
            uint32_t bf[8][2];
            #pragma unroll
            for (int n = 0; n < 8; n++) {
                uint2 w = *(const uint2*)(Bs + ((ki * 16 + warpN * 8 + n) * 64 + lane * 2));
                bf[n][0] = w.x; bf[n][1] = w.y;
            }
            #pragma unroll
            for (int m = 0; m < 2; m++)
                #pragma unroll
                for (int n = 0; n < 8; n++) MMA16(acc[m][n], af[m], bf[n]);
        }
    }

    // epilogue
    int g = lane >> 2, tg = lane & 3;
    int rowBase = mt * BM + warpM * 32;
    int colBase = nt * BN + warpN * 64;
    #pragma unroll
    for (int m = 0; m < 2; m++) {
        int r0 = rowBase + m * 16 + g;
        #pragma unroll
        for (int n = 0; n < 8; n++) {
            int c = colBase + n * 8 + tg * 2;
            float2 bb = *(const float2*)(bias + c);
            float2 o0 = { acc[m][n][0] + bb.x, acc[m][n][1] + bb.y };
            float2 o1 = { acc[m][n][2] + bb.x, acc[m][n][3] + bb.y };
            *(float2*)(C + (size_t)r0 * NN + c) = o0;
            *(float2*)(C + (size_t)(r0 + 8) * NN + c) = o1;
        }
    }
}

// ---------------- in-place row log-softmax ----------------
__global__ void k_lsm(float* __restrict__ out) {
    int i = blockIdx.x;
    int t = threadIdx.x;                 // 256
    __shared__ float row[NN];
    __shared__ float red[256];

    float m = -1e30f;
    for (int j = t; j < NN; j += 256) {
        float v = out[(size_t)i * NN + j];
        row[j] = v;
        m = fmaxf(m, v);
    }
    red[t] = m;
    __syncthreads();
    #pragma unroll
    for (int o = 128; o; o >>= 1) {
        if (t < o) red[t] = fmaxf(red[t], red[t + o]);
        __syncthreads();
    }
    float mx = red[0];
    __syncthreads();

    float s = 0.f;
    for (int j = t; j < NN; j += 256) s += __expf(row[j] - mx);
    red[t] = s;
    __syncthreads();
    #pragma unroll
    for (int o = 128; o; o >>= 1) {
        if (t < o) red[t] += red[t + o];
        __syncthreads();
    }
    float lse = logf(red[0]) + mx;

    for (int j = t; j < NN; j += 256) out[(size_t)i * NN + j] = row[j] - lse;
}

// ---------------- launch ----------------
extern "C" void kernel_launch(void* const* d_in, const int* in_sizes, int n_in,
                              void* d_out, int out_size) {
    const float* dist   = (const float*)d_in[0];
    const float* emb    = (const float*)d_in[1];
    const float* llw    = (const float*)d_in[2];
    const float* llb    = (const float*)d_in[3];
    const float* lrw    = (const float*)d_in[4];
    const float* ew     = (const float*)d_in[5];
    const float* edge_b = (const float*)d_in[6];
    const float* combw  = (const float*)d_in[7];
    const float* combb  = (const float*)d_in[8];
    const int*   stops  = (const int*)d_in[9];
    const int*   wk     = (const int*)d_in[10];
    const int*   vh     = (const int*)d_in[11];
    float* out = (float*)d_out;

    k_zero<<<(NN * DD + 255) / 256, 256>>>();
    k_scatter<<<(NSTOP + 255) / 256, 256>>>(stops);
    k_norm<<<NN, DD>>>(emb);
    k_compact<<<NN, DD>>>(emb);
    k_agg2<<<NSTOP, 256>>>();
    k_pref<<<NN, PP>>>(emb, llw, llb, lrw, ew);

    int tot = NN * (KPAD / 2);
    k_fill_a<<<(tot + 255) / 256, 256>>>(dist, edge_b, wk, vh);
    k_fill_b<<<(tot + 255) / 256, 256>>>(combw);

    cudaFuncSetAttribute(k_gemm_mma, cudaFuncAttributeMaxDynamicSharedMemorySize, GEMM_SMEM);
    dim3 gg(NN / BN, NN / BM);
    k_gemm_mma<<<gg, 256, GEMM_SMEM>>>(combb, out);

    k_lsm<<<NN, 256>>>(out);
}